// round 1
// baseline (speedup 1.0000x reference)
#include <cuda_runtime.h>

#define NN_MAX 100000
#define CH 64

// 100000 nodes * 128 floats = 51.2 MB scratch for precomputed P|Q
__device__ float g_PQ[(size_t)NN_MAX * 128];
__device__ int g_is64;

// ---------------------------------------------------------------------------
// Detect whether edge_index is int64 or int32. int64 little-endian words for
// values < 2^31 are [v, 0]; if the odd 32-bit words of the first 64 entries
// are all zero, it's int64. (If int32, those words are random indices in
// [0,1e5): P(all zero) ~ 1e-320.)
// ---------------------------------------------------------------------------
__global__ void detect_kernel(const unsigned* __restrict__ ei_raw) {
    int is64 = 1;
    for (int k = 0; k < 64; k++) {
        if (ei_raw[2 * k + 1] != 0u) { is64 = 0; break; }
    }
    g_is64 = is64;
}

__global__ void zero_kernel(float4* __restrict__ out, int n4) {
    int i = blockIdx.x * blockDim.x + threadIdx.x;
    if (i < n4) out[i] = make_float4(0.f, 0.f, 0.f, 0.f);
}

// ---------------------------------------------------------------------------
// Per-node precompute: PQ[n][0:64]  = x[n] @ W1[0:64]   (source part)
//                      PQ[n][64:128]= x[n] @ W1[64:128] (target part)
// One warp per node; lane owns channels {2l, 2l+1}.
// ---------------------------------------------------------------------------
__global__ __launch_bounds__(256) void node_precompute(
    const float* __restrict__ x, const float* __restrict__ W1, int n_nodes) {
    __shared__ float sW[128 * CH];  // W1 rows 0..127, 32 KB
    for (int t = threadIdx.x; t < 128 * CH / 4; t += blockDim.x)
        ((float4*)sW)[t] = ((const float4*)W1)[t];
    __syncthreads();

    int warp = threadIdx.x >> 5, lane = threadIdx.x & 31;
    int node = blockIdx.x * (blockDim.x >> 5) + warp;
    if (node >= n_nodes) return;

    float x0 = x[(size_t)node * CH + lane];
    float x1 = x[(size_t)node * CH + 32 + lane];
    int c = 2 * lane;
    float px = 0.f, py = 0.f, qx = 0.f, qy = 0.f;

#pragma unroll
    for (int k = 0; k < 32; k++) {
        float xk = __shfl_sync(0xFFFFFFFFu, x0, k);
        float2 wp = *(const float2*)&sW[k * CH + c];
        float2 wq = *(const float2*)&sW[(64 + k) * CH + c];
        px += xk * wp.x; py += xk * wp.y;
        qx += xk * wq.x; qy += xk * wq.y;
    }
#pragma unroll
    for (int k = 0; k < 32; k++) {
        float xk = __shfl_sync(0xFFFFFFFFu, x1, k);
        float2 wp = *(const float2*)&sW[(32 + k) * CH + c];
        float2 wq = *(const float2*)&sW[(96 + k) * CH + c];
        px += xk * wp.x; py += xk * wp.y;
        qx += xk * wq.x; qy += xk * wq.y;
    }
    float* pq = &g_PQ[(size_t)node * 128];
    *(float2*)&pq[c]      = make_float2(px, py);
    *(float2*)&pq[64 + c] = make_float2(qx, qy);
}

// ---------------------------------------------------------------------------
// Per-edge kernel: warp per edge.
//   h = PQ[i][0:64] + PQ[j][64:128] + ea @ W1c + b1
//   g = gelu(layernorm(h))      (exact erf gelu)
//   m = g @ W2 + b2
//   atomically scatter m onto out[j]
// ---------------------------------------------------------------------------
__global__ __launch_bounds__(256) void edge_kernel(
    const void* __restrict__ ei, const float* __restrict__ ea,
    const float* __restrict__ W1, const float* __restrict__ b1,
    const float* __restrict__ gamma, const float* __restrict__ beta,
    const float* __restrict__ W2, const float* __restrict__ b2,
    float* __restrict__ out, int n_edges) {
    __shared__ float sW1c[32 * CH];   //  8 KB : W1 rows 128..159
    __shared__ float sW2[CH * CH];    // 16 KB
    __shared__ float sb1[CH], sb2[CH], sgm[CH], sbt[CH];
    __shared__ float sea[8][32];
    __shared__ float sg[8][CH];

    for (int t = threadIdx.x; t < 32 * CH / 4; t += 256)
        ((float4*)sW1c)[t] = ((const float4*)(W1 + 128 * CH))[t];
    for (int t = threadIdx.x; t < CH * CH / 4; t += 256)
        ((float4*)sW2)[t] = ((const float4*)W2)[t];
    if (threadIdx.x < CH) {
        sb1[threadIdx.x] = b1[threadIdx.x];
        sb2[threadIdx.x] = b2[threadIdx.x];
        sgm[threadIdx.x] = gamma[threadIdx.x];
        sbt[threadIdx.x] = beta[threadIdx.x];
    }
    __syncthreads();

    int warp = threadIdx.x >> 5, lane = threadIdx.x & 31;
    int e = blockIdx.x * 8 + warp;
    if (e >= n_edges) return;

    int i, j;
    if (g_is64) {
        const long long* p = (const long long*)ei;
        i = (int)p[e]; j = (int)p[(size_t)n_edges + e];
    } else {
        const int* p = (const int*)ei;
        i = p[e]; j = p[(size_t)n_edges + e];
    }

    int c = 2 * lane;
    const float* pqi = &g_PQ[(size_t)i * 128];
    const float* pqj = &g_PQ[(size_t)j * 128];
    float2 hp = *(const float2*)&pqi[c];
    float2 hq = *(const float2*)&pqj[64 + c];
    float hx = hp.x + hq.x + sb1[c];
    float hy = hp.y + hq.y + sb1[c + 1];

    sea[warp][lane] = ea[(size_t)e * 32 + lane];
    __syncwarp();
#pragma unroll
    for (int k = 0; k < 32; k++) {
        float a = sea[warp][k];
        float2 w = *(const float2*)&sW1c[k * CH + c];
        hx += a * w.x; hy += a * w.y;
    }

    // LayerNorm over 64 channels (2 per lane)
    float s = hx + hy;
    float ss = hx * hx + hy * hy;
#pragma unroll
    for (int o = 16; o; o >>= 1) {
        s  += __shfl_xor_sync(0xFFFFFFFFu, s,  o);
        ss += __shfl_xor_sync(0xFFFFFFFFu, ss, o);
    }
    float mu   = s * (1.f / 64.f);
    float var  = ss * (1.f / 64.f) - mu * mu;
    float rstd = rsqrtf(var + 1e-5f);

    float gx = (hx - mu) * rstd * sgm[c]     + sbt[c];
    float gy = (hy - mu) * rstd * sgm[c + 1] + sbt[c + 1];
    // exact gelu: 0.5 * v * (1 + erf(v / sqrt(2)))
    gx = 0.5f * gx * (1.f + erff(gx * 0.7071067811865476f));
    gy = 0.5f * gy * (1.f + erff(gy * 0.7071067811865476f));

    sg[warp][c] = gx;
    sg[warp][c + 1] = gy;
    __syncwarp();

    float mx = sb2[c], my = sb2[c + 1];
#pragma unroll
    for (int k = 0; k < CH; k++) {
        float a = sg[warp][k];
        float2 w = *(const float2*)&sW2[k * CH + c];
        mx += a * w.x; my += a * w.y;
    }

    float* dst = out + (size_t)j * CH + c;
    asm volatile("red.global.add.v2.f32 [%0], {%1, %2};"
                 :: "l"(dst), "f"(mx), "f"(my) : "memory");
}

// ---------------------------------------------------------------------------
extern "C" void kernel_launch(void* const* d_in, const int* in_sizes, int n_in,
                              void* d_out, int out_size) {
    const float* x     = (const float*)d_in[0];
    const void*  ei    = d_in[1];
    const float* ea    = (const float*)d_in[2];
    const float* W1    = (const float*)d_in[3];
    const float* b1    = (const float*)d_in[4];
    const float* gamma = (const float*)d_in[5];
    const float* beta  = (const float*)d_in[6];
    const float* W2    = (const float*)d_in[7];
    const float* b2    = (const float*)d_in[8];
    float* out = (float*)d_out;

    int n_nodes = in_sizes[0] / CH;
    int n_edges = in_sizes[2] / 32;

    detect_kernel<<<1, 1>>>((const unsigned*)ei);

    int n4 = out_size / 4;
    zero_kernel<<<(n4 + 255) / 256, 256>>>((float4*)out, n4);

    node_precompute<<<(n_nodes + 7) / 8, 256>>>(x, W1, n_nodes);

    edge_kernel<<<(n_edges + 7) / 8, 256>>>(ei, ea, W1, b1, gamma, beta,
                                            W2, b2, out, n_edges);
}

// round 2
// speedup vs baseline: 3.5344x; 3.5344x over previous
#include <cuda_runtime.h>

#define NN_MAX 100000
#define CH 64
#define WP 72          // padded smem row (bank-conflict-free: 72%32=8)
#define TILE_E 16
#define WARPS 8
#define NBLK 1184

__device__ float g_PQ[(size_t)NN_MAX * 128];
__device__ int g_is64;

__device__ __forceinline__ unsigned f2tf32(float f) {
    unsigned u;
    asm("cvt.rna.tf32.f32 %0, %1;" : "=r"(u) : "f"(f));
    return u;
}

__device__ __forceinline__ void mma_tf32(float c[4], unsigned a0, unsigned a1,
                                         unsigned a2, unsigned a3,
                                         unsigned b0, unsigned b1) {
    asm volatile(
        "mma.sync.aligned.m16n8k8.row.col.f32.tf32.tf32.f32 "
        "{%0,%1,%2,%3}, {%4,%5,%6,%7}, {%8,%9}, {%0,%1,%2,%3};"
        : "+f"(c[0]), "+f"(c[1]), "+f"(c[2]), "+f"(c[3])
        : "r"(a0), "r"(a1), "r"(a2), "r"(a3), "r"(b0), "r"(b1));
}

// ---------------------------------------------------------------------------
__global__ void detect_kernel(const unsigned* __restrict__ ei_raw) {
    int is64 = 1;
    for (int k = 0; k < 64; k++)
        if (ei_raw[2 * k + 1] != 0u) { is64 = 0; break; }
    g_is64 = is64;
}

__global__ void zero_kernel(float4* __restrict__ out, int n4) {
    int i = blockIdx.x * blockDim.x + threadIdx.x;
    if (i < n4) out[i] = make_float4(0.f, 0.f, 0.f, 0.f);
}

// ---------------------------------------------------------------------------
// Per-node precompute: PQ[n][0:64] = x[n]@W1[0:64], PQ[n][64:128] = x[n]@W1[64:128]
// ---------------------------------------------------------------------------
__global__ __launch_bounds__(256) void node_precompute(
    const float* __restrict__ x, const float* __restrict__ W1, int n_nodes) {
    __shared__ float sW[128 * CH];
    for (int t = threadIdx.x; t < 128 * CH / 4; t += blockDim.x)
        ((float4*)sW)[t] = ((const float4*)W1)[t];
    __syncthreads();

    int warp = threadIdx.x >> 5, lane = threadIdx.x & 31;
    int node = blockIdx.x * (blockDim.x >> 5) + warp;
    if (node >= n_nodes) return;

    float x0 = x[(size_t)node * CH + lane];
    float x1 = x[(size_t)node * CH + 32 + lane];
    int c = 2 * lane;
    float px = 0.f, py = 0.f, qx = 0.f, qy = 0.f;
#pragma unroll
    for (int k = 0; k < 32; k++) {
        float xk = __shfl_sync(0xFFFFFFFFu, x0, k);
        float2 wp = *(const float2*)&sW[k * CH + c];
        float2 wq = *(const float2*)&sW[(64 + k) * CH + c];
        px += xk * wp.x; py += xk * wp.y;
        qx += xk * wq.x; qy += xk * wq.y;
    }
#pragma unroll
    for (int k = 0; k < 32; k++) {
        float xk = __shfl_sync(0xFFFFFFFFu, x1, k);
        float2 wp = *(const float2*)&sW[(32 + k) * CH + c];
        float2 wq = *(const float2*)&sW[(96 + k) * CH + c];
        px += xk * wp.x; py += xk * wp.y;
        qx += xk * wq.x; qy += xk * wq.y;
    }
    float* pq = &g_PQ[(size_t)node * 128];
    *(float2*)&pq[c]      = make_float2(px, py);
    *(float2*)&pq[64 + c] = make_float2(qx, qy);
}

// ---------------------------------------------------------------------------
// Edge kernel: one warp = 16 edges, both GEMMs on tf32 tensor cores.
// ---------------------------------------------------------------------------
__global__ __launch_bounds__(256, 2) void edge_kernel(
    const void* __restrict__ ei, const float* __restrict__ ea,
    const float* __restrict__ W1, const float* __restrict__ b1,
    const float* __restrict__ gamma, const float* __restrict__ beta,
    const float* __restrict__ W2, const float* __restrict__ b2,
    float* __restrict__ out, int n_edges) {
    __shared__ unsigned sW1c[32 * WP];   // tf32 W1 rows 128..159
    __shared__ unsigned sW2[64 * WP];    // tf32 W2
    __shared__ float sb1[CH], sb2[CH], sgm[CH], sbt[CH];

    for (int t = threadIdx.x; t < 32 * CH; t += 256) {
        int k = t >> 6, n = t & 63;
        sW1c[k * WP + n] = f2tf32(W1[(size_t)(128 + k) * CH + n]);
    }
    for (int t = threadIdx.x; t < 64 * CH; t += 256) {
        int k = t >> 6, n = t & 63;
        sW2[k * WP + n] = f2tf32(W2[(size_t)k * CH + n]);
    }
    if (threadIdx.x < CH) {
        sb1[threadIdx.x] = b1[threadIdx.x];
        sb2[threadIdx.x] = b2[threadIdx.x];
        sgm[threadIdx.x] = gamma[threadIdx.x];
        sbt[threadIdx.x] = beta[threadIdx.x];
    }
    __syncthreads();

    const int warp = threadIdx.x >> 5, lane = threadIdx.x & 31;
    const int gr = lane >> 2;      // groupID (row within tile)
    const int q  = lane & 3;       // threadID_in_group
    const int is64 = g_is64;
    const unsigned FULL = 0xFFFFFFFFu;
    const int n_tiles = (n_edges + TILE_E - 1) / TILE_E;

    for (int tile = blockIdx.x * WARPS + warp; tile < n_tiles;
         tile += gridDim.x * WARPS) {
        const int base = tile * TILE_E;

        // ---- edge indices: lanes 0-15 load i, 16-31 load j ----
        int v = 0;
        {
            int e = base + (lane & 15);
            if (e < n_edges) {
                if (is64) {
                    const long long* p = (const long long*)ei;
                    v = (int)((lane < 16) ? p[e] : p[(size_t)n_edges + e]);
                } else {
                    const int* p = (const int*)ei;
                    v = (lane < 16) ? p[e] : p[(size_t)n_edges + e];
                }
            }
        }
        const int r0 = gr, r1 = gr + 8;
        const int i0 = __shfl_sync(FULL, v, r0), j0 = __shfl_sync(FULL, v, 16 + r0);
        const int i1 = __shfl_sync(FULL, v, r1), j1 = __shfl_sync(FULL, v, 16 + r1);
        const bool v0 = (base + r0) < n_edges, v1 = (base + r1) < n_edges;

        // ---- GEMM1: h = ea @ W1c  (C layout: h[t][0..3]) ----
        float h[8][4];
#pragma unroll
        for (int t = 0; t < 8; t++)
            h[t][0] = h[t][1] = h[t][2] = h[t][3] = 0.f;

#pragma unroll
        for (int s = 0; s < 4; s++) {
            unsigned a0 = 0, a1 = 0, a2 = 0, a3 = 0;
            if (v0) {
                const float* r = ea + (size_t)(base + r0) * 32 + 8 * s;
                a0 = f2tf32(r[q]); a2 = f2tf32(r[q + 4]);
            }
            if (v1) {
                const float* r = ea + (size_t)(base + r1) * 32 + 8 * s;
                a1 = f2tf32(r[q]); a3 = f2tf32(r[q + 4]);
            }
#pragma unroll
            for (int t = 0; t < 8; t++) {
                unsigned b0 = sW1c[(8 * s + q) * WP + 8 * t + gr];
                unsigned b1f = sW1c[(8 * s + q + 4) * WP + 8 * t + gr];
                mma_tf32(h[t], a0, a1, a2, a3, b0, b1f);
            }
        }

        // ---- add PQ[i] (src part) + PQ[j] (dst part) + b1 ----
#pragma unroll
        for (int t = 0; t < 8; t++) {
            int c = 8 * t + 2 * q;
            if (v0) {
                float2 pi = *(const float2*)&g_PQ[(size_t)i0 * 128 + c];
                float2 pj = *(const float2*)&g_PQ[(size_t)j0 * 128 + 64 + c];
                h[t][0] += pi.x + pj.x + sb1[c];
                h[t][1] += pi.y + pj.y + sb1[c + 1];
            }
            if (v1) {
                float2 pi = *(const float2*)&g_PQ[(size_t)i1 * 128 + c];
                float2 pj = *(const float2*)&g_PQ[(size_t)j1 * 128 + 64 + c];
                h[t][2] += pi.x + pj.x + sb1[c];
                h[t][3] += pi.y + pj.y + sb1[c + 1];
            }
        }

        // ---- LayerNorm (per edge row, 64 ch spread over quad x 8 tiles) ----
        float s0 = 0, ss0 = 0, s1 = 0, ss1 = 0;
#pragma unroll
        for (int t = 0; t < 8; t++) {
            s0 += h[t][0] + h[t][1]; ss0 += h[t][0] * h[t][0] + h[t][1] * h[t][1];
            s1 += h[t][2] + h[t][3]; ss1 += h[t][2] * h[t][2] + h[t][3] * h[t][3];
        }
#pragma unroll
        for (int o = 1; o <= 2; o <<= 1) {
            s0 += __shfl_xor_sync(FULL, s0, o); ss0 += __shfl_xor_sync(FULL, ss0, o);
            s1 += __shfl_xor_sync(FULL, s1, o); ss1 += __shfl_xor_sync(FULL, ss1, o);
        }
        float mu0 = s0 * (1.f / 64.f), rs0 = rsqrtf(ss0 * (1.f / 64.f) - mu0 * mu0 + 1e-5f);
        float mu1 = s1 * (1.f / 64.f), rs1 = rsqrtf(ss1 * (1.f / 64.f) - mu1 * mu1 + 1e-5f);

        // ---- gamma/beta + exact GELU, in place ----
#pragma unroll
        for (int t = 0; t < 8; t++) {
            int c = 8 * t + 2 * q;
            float g00 = (h[t][0] - mu0) * rs0 * sgm[c]     + sbt[c];
            float g01 = (h[t][1] - mu0) * rs0 * sgm[c + 1] + sbt[c + 1];
            float g10 = (h[t][2] - mu1) * rs1 * sgm[c]     + sbt[c];
            float g11 = (h[t][3] - mu1) * rs1 * sgm[c + 1] + sbt[c + 1];
            h[t][0] = 0.5f * g00 * (1.f + erff(g00 * 0.7071067811865476f));
            h[t][1] = 0.5f * g01 * (1.f + erff(g01 * 0.7071067811865476f));
            h[t][2] = 0.5f * g10 * (1.f + erff(g10 * 0.7071067811865476f));
            h[t][3] = 0.5f * g11 * (1.f + erff(g11 * 0.7071067811865476f));
        }

        // ---- GEMM2: m = g @ W2 ; remap C-layout -> A-frags via quad shuffles ----
        float m[8][4];
#pragma unroll
        for (int t = 0; t < 8; t++)
            m[t][0] = m[t][1] = m[t][2] = m[t][3] = 0.f;

        const int srcA = (lane & ~3) | (q >> 1);
        const int srcB = srcA + 2;
#pragma unroll
        for (int s = 0; s < 8; s++) {
            float t00 = __shfl_sync(FULL, h[s][0], srcA);
            float t01 = __shfl_sync(FULL, h[s][1], srcA);
            float t10 = __shfl_sync(FULL, h[s][2], srcA);
            float t11 = __shfl_sync(FULL, h[s][3], srcA);
            float u00 = __shfl_sync(FULL, h[s][0], srcB);
            float u01 = __shfl_sync(FULL, h[s][1], srcB);
            float u10 = __shfl_sync(FULL, h[s][2], srcB);
            float u11 = __shfl_sync(FULL, h[s][3], srcB);
            unsigned a0 = f2tf32((q & 1) ? t01 : t00);
            unsigned a1 = f2tf32((q & 1) ? t11 : t10);
            unsigned a2 = f2tf32((q & 1) ? u01 : u00);
            unsigned a3 = f2tf32((q & 1) ? u11 : u10);
#pragma unroll
            for (int t = 0; t < 8; t++) {
                unsigned b0 = sW2[(8 * s + q) * WP + 8 * t + gr];
                unsigned b1f = sW2[(8 * s + q + 4) * WP + 8 * t + gr];
                mma_tf32(m[t], a0, a1, a2, a3, b0, b1f);
            }
        }

        // ---- scatter-add (+b2) onto target nodes ----
#pragma unroll
        for (int t = 0; t < 8; t++) {
            int c = 8 * t + 2 * q;
            if (v0) {
                float mx = m[t][0] + sb2[c], my = m[t][1] + sb2[c + 1];
                asm volatile("red.global.add.v2.f32 [%0], {%1, %2};"
                             :: "l"(out + (size_t)j0 * CH + c), "f"(mx), "f"(my)
                             : "memory");
            }
            if (v1) {
                float mx = m[t][2] + sb2[c], my = m[t][3] + sb2[c + 1];
                asm volatile("red.global.add.v2.f32 [%0], {%1, %2};"
                             :: "l"(out + (size_t)j1 * CH + c), "f"(mx), "f"(my)
                             : "memory");
            }
        }
    }
}

// ---------------------------------------------------------------------------
extern "C" void kernel_launch(void* const* d_in, const int* in_sizes, int n_in,
                              void* d_out, int out_size) {
    const float* x     = (const float*)d_in[0];
    const void*  ei    = d_in[1];
    const float* ea    = (const float*)d_in[2];
    const float* W1    = (const float*)d_in[3];
    const float* b1    = (const float*)d_in[4];
    const float* gamma = (const float*)d_in[5];
    const float* beta  = (const float*)d_in[6];
    const float* W2    = (const float*)d_in[7];
    const float* b2    = (const float*)d_in[8];
    float* out = (float*)d_out;

    int n_nodes = in_sizes[0] / CH;
    int n_edges = in_sizes[2] / 32;

    detect_kernel<<<1, 1>>>((const unsigned*)ei);

    int n4 = out_size / 4;
    zero_kernel<<<(n4 + 255) / 256, 256>>>((float4*)out, n4);

    node_precompute<<<(n_nodes + 7) / 8, 256>>>(x, W1, n_nodes);

    edge_kernel<<<NBLK, 256>>>(ei, ea, W1, b1, gamma, beta, W2, b2, out, n_edges);
}

// round 3
// speedup vs baseline: 4.7758x; 1.3512x over previous
#include <cuda_runtime.h>

#define NN_MAX 100000
#define CH 64
#define TILE_E 16
#define WARPS 8
#define NBLK 1184
#define WEA 36     // padded ea row (words): bank=(4r+8s+q)%32 conflict-free

__device__ float g_PQ[(size_t)NN_MAX * 128];
__device__ int g_is64;

__device__ __forceinline__ unsigned f2tf32(float f) {
    unsigned u;
    asm("cvt.rna.tf32.f32 %0, %1;" : "=r"(u) : "f"(f));
    return u;
}

__device__ __forceinline__ void mma_tf32(float c[4], unsigned a0, unsigned a1,
                                         unsigned a2, unsigned a3,
                                         unsigned b0, unsigned b1) {
    asm volatile(
        "mma.sync.aligned.m16n8k8.row.col.f32.tf32.tf32.f32 "
        "{%0,%1,%2,%3}, {%4,%5,%6,%7}, {%8,%9}, {%0,%1,%2,%3};"
        : "+f"(c[0]), "+f"(c[1]), "+f"(c[2]), "+f"(c[3])
        : "r"(a0), "r"(a1), "r"(a2), "r"(a3), "r"(b0), "r"(b1));
}

// ---------------------------------------------------------------------------
__global__ void detect_kernel(const unsigned* __restrict__ ei_raw) {
    int is64 = 1;
    for (int k = 0; k < 64; k++)
        if (ei_raw[2 * k + 1] != 0u) { is64 = 0; break; }
    g_is64 = is64;
}

__global__ void zero_kernel(float4* __restrict__ out, int n4) {
    int i = blockIdx.x * blockDim.x + threadIdx.x;
    if (i < n4) out[i] = make_float4(0.f, 0.f, 0.f, 0.f);
}

// ---------------------------------------------------------------------------
// Tensorized node precompute: PQ[n][0:128] = x[n] @ Wcat[64 x 128]
// Wcat[k][n] = (n<64) ? W1[k][n] : W1[64+k][n-64]
// One warp = 16 nodes. B weights paired in smem for LDS.64.
// ---------------------------------------------------------------------------
__global__ __launch_bounds__(256) void node_precompute(
    const float* __restrict__ x, const float* __restrict__ W1, int n_nodes) {
    __shared__ uint2 sBp[8 * 16 * 32];   // 32 KB: (s, t, lane) -> {W[8s+q][n], W[8s+q+4][n]}, n=8t+gr

    for (int idx = threadIdx.x; idx < 8 * 16 * 32; idx += 256) {
        int lane = idx & 31, tt = (idx >> 5) & 15, s = idx >> 9;
        int gr = lane >> 2, q = lane & 3;
        int n = 8 * tt + gr;
        int k0 = 8 * s + q, k1 = k0 + 4;
        float w0 = (n < 64) ? W1[(size_t)k0 * CH + n] : W1[(size_t)(64 + k0) * CH + n - 64];
        float w1 = (n < 64) ? W1[(size_t)k1 * CH + n] : W1[(size_t)(64 + k1) * CH + n - 64];
        sBp[idx] = make_uint2(f2tf32(w0), f2tf32(w1));
    }
    __syncthreads();

    const int warp = threadIdx.x >> 5, lane = threadIdx.x & 31;
    const int gr = lane >> 2, q = lane & 3;
    const int tile = blockIdx.x * 8 + warp;
    const int base = tile * 16;
    if (base >= n_nodes) return;
    const int r0 = base + gr, r1 = base + gr + 8;
    const bool v0 = r0 < n_nodes, v1 = r1 < n_nodes;

    float h[16][4];
#pragma unroll
    for (int t = 0; t < 16; t++)
        h[t][0] = h[t][1] = h[t][2] = h[t][3] = 0.f;

#pragma unroll
    for (int s = 0; s < 8; s++) {
        unsigned a0 = 0, a1 = 0, a2 = 0, a3 = 0;
        if (v0) {
            const float* r = x + (size_t)r0 * CH + 8 * s;
            a0 = f2tf32(r[q]); a2 = f2tf32(r[q + 4]);
        }
        if (v1) {
            const float* r = x + (size_t)r1 * CH + 8 * s;
            a1 = f2tf32(r[q]); a3 = f2tf32(r[q + 4]);
        }
#pragma unroll
        for (int t = 0; t < 16; t++) {
            uint2 b = sBp[(s * 16 + t) * 32 + lane];
            mma_tf32(h[t], a0, a1, a2, a3, b.x, b.y);
        }
    }

#pragma unroll
    for (int t = 0; t < 16; t++) {
        int c = 8 * t + 2 * q;
        if (v0) *(float2*)&g_PQ[(size_t)r0 * 128 + c] = make_float2(h[t][0], h[t][1]);
        if (v1) *(float2*)&g_PQ[(size_t)r1 * 128 + c] = make_float2(h[t][2], h[t][3]);
    }
}

// ---------------------------------------------------------------------------
// Edge kernel: warp = 16 edges, tf32 mma for both GEMMs.
// ---------------------------------------------------------------------------
__global__ __launch_bounds__(256, 2) void edge_kernel(
    const void* __restrict__ ei, const float* __restrict__ ea,
    const float* __restrict__ W1, const float* __restrict__ b1,
    const float* __restrict__ gamma, const float* __restrict__ beta,
    const float* __restrict__ W2, const float* __restrict__ b2,
    float* __restrict__ out, int n_edges) {
    __shared__ uint2 sW1p[4 * 8 * 32];        //  8 KB
    __shared__ uint2 sW2p[8 * 8 * 32];        // 16 KB
    __shared__ float sea[WARPS][16 * WEA];    // 18 KB
    __shared__ float sb1[CH], sb2[CH], sgm[CH], sbt[CH];

    for (int idx = threadIdx.x; idx < 4 * 8 * 32; idx += 256) {
        int lane = idx & 31, tt = (idx >> 5) & 7, s = idx >> 8;
        int gr = lane >> 2, q = lane & 3;
        int n = 8 * tt + gr;
        int k0 = 8 * s + q, k1 = k0 + 4;
        sW1p[idx] = make_uint2(f2tf32(W1[(size_t)(128 + k0) * CH + n]),
                               f2tf32(W1[(size_t)(128 + k1) * CH + n]));
    }
    for (int idx = threadIdx.x; idx < 8 * 8 * 32; idx += 256) {
        int lane = idx & 31, tt = (idx >> 5) & 7, s = idx >> 8;
        int gr = lane >> 2, q = lane & 3;
        int n = 8 * tt + gr;
        int k0 = 8 * s + q, k1 = k0 + 4;
        sW2p[idx] = make_uint2(f2tf32(W2[(size_t)k0 * CH + n]),
                               f2tf32(W2[(size_t)k1 * CH + n]));
    }
    if (threadIdx.x < CH) {
        sb1[threadIdx.x] = b1[threadIdx.x];
        sb2[threadIdx.x] = b2[threadIdx.x];
        sgm[threadIdx.x] = gamma[threadIdx.x];
        sbt[threadIdx.x] = beta[threadIdx.x];
    }
    __syncthreads();

    const int warp = threadIdx.x >> 5, lane = threadIdx.x & 31;
    const int gr = lane >> 2;
    const int q  = lane & 3;
    const int is64 = g_is64;
    const unsigned FULL = 0xFFFFFFFFu;
    const int n_tiles = (n_edges + TILE_E - 1) / TILE_E;
    float* mea = sea[warp];

    for (int tile = blockIdx.x * WARPS + warp; tile < n_tiles;
         tile += gridDim.x * WARPS) {
        const int base = tile * TILE_E;

        // ---- edge indices ----
        int v = 0;
        {
            int e = base + (lane & 15);
            if (e < n_edges) {
                if (is64) {
                    const long long* p = (const long long*)ei;
                    v = (int)((lane < 16) ? p[e] : p[(size_t)n_edges + e]);
                } else {
                    const int* p = (const int*)ei;
                    v = (lane < 16) ? p[e] : p[(size_t)n_edges + e];
                }
            }
        }
        const int r0 = gr, r1 = gr + 8;
        const int i0 = __shfl_sync(FULL, v, r0), j0 = __shfl_sync(FULL, v, 16 + r0);
        const int i1 = __shfl_sync(FULL, v, r1), j1 = __shfl_sync(FULL, v, 16 + r1);
        const bool v0 = (base + r0) < n_edges, v1 = (base + r1) < n_edges;

        // ---- stage ea tile to smem (coalesced LDG.128) ----
        __syncwarp();
        {
            const float* src = ea + (size_t)base * 32;
#pragma unroll
            for (int it = 0; it < 4; it++) {
                int idx = lane + 32 * it;          // float4 index 0..127
                int row = idx >> 3, c4 = idx & 7;
                float4 val = make_float4(0.f, 0.f, 0.f, 0.f);
                if (base + row < n_edges) val = *(const float4*)(src + row * 32 + c4 * 4);
                *(float4*)&mea[row * WEA + c4 * 4] = val;
            }
        }
        __syncwarp();

        // ---- GEMM1: h = ea @ W1c ----
        float h[8][4];
#pragma unroll
        for (int t = 0; t < 8; t++)
            h[t][0] = h[t][1] = h[t][2] = h[t][3] = 0.f;

#pragma unroll
        for (int s = 0; s < 4; s++) {
            unsigned a0 = f2tf32(mea[r0 * WEA + 8 * s + q]);
            unsigned a2 = f2tf32(mea[r0 * WEA + 8 * s + q + 4]);
            unsigned a1 = f2tf32(mea[r1 * WEA + 8 * s + q]);
            unsigned a3 = f2tf32(mea[r1 * WEA + 8 * s + q + 4]);
#pragma unroll
            for (int t = 0; t < 8; t++) {
                uint2 b = sW1p[(s * 8 + t) * 32 + lane];
                mma_tf32(h[t], a0, a1, a2, a3, b.x, b.y);
            }
        }

        // ---- add PQ[i] + PQ[j] + b1 ----
#pragma unroll
        for (int t = 0; t < 8; t++) {
            int c = 8 * t + 2 * q;
            if (v0) {
                float2 pi = *(const float2*)&g_PQ[(size_t)i0 * 128 + c];
                float2 pj = *(const float2*)&g_PQ[(size_t)j0 * 128 + 64 + c];
                h[t][0] += pi.x + pj.x + sb1[c];
                h[t][1] += pi.y + pj.y + sb1[c + 1];
            }
            if (v1) {
                float2 pi = *(const float2*)&g_PQ[(size_t)i1 * 128 + c];
                float2 pj = *(const float2*)&g_PQ[(size_t)j1 * 128 + 64 + c];
                h[t][2] += pi.x + pj.x + sb1[c];
                h[t][3] += pi.y + pj.y + sb1[c + 1];
            }
        }

        // ---- LayerNorm ----
        float s0 = 0, ss0 = 0, s1 = 0, ss1 = 0;
#pragma unroll
        for (int t = 0; t < 8; t++) {
            s0 += h[t][0] + h[t][1]; ss0 += h[t][0] * h[t][0] + h[t][1] * h[t][1];
            s1 += h[t][2] + h[t][3]; ss1 += h[t][2] * h[t][2] + h[t][3] * h[t][3];
        }
#pragma unroll
        for (int o = 1; o <= 2; o <<= 1) {
            s0 += __shfl_xor_sync(FULL, s0, o); ss0 += __shfl_xor_sync(FULL, ss0, o);
            s1 += __shfl_xor_sync(FULL, s1, o); ss1 += __shfl_xor_sync(FULL, ss1, o);
        }
        float mu0 = s0 * (1.f / 64.f), rs0 = rsqrtf(ss0 * (1.f / 64.f) - mu0 * mu0 + 1e-5f);
        float mu1 = s1 * (1.f / 64.f), rs1 = rsqrtf(ss1 * (1.f / 64.f) - mu1 * mu1 + 1e-5f);

        // ---- gamma/beta + exact GELU ----
#pragma unroll
        for (int t = 0; t < 8; t++) {
            int c = 8 * t + 2 * q;
            float g00 = (h[t][0] - mu0) * rs0 * sgm[c]     + sbt[c];
            float g01 = (h[t][1] - mu0) * rs0 * sgm[c + 1] + sbt[c + 1];
            float g10 = (h[t][2] - mu1) * rs1 * sgm[c]     + sbt[c];
            float g11 = (h[t][3] - mu1) * rs1 * sgm[c + 1] + sbt[c + 1];
            h[t][0] = 0.5f * g00 * (1.f + erff(g00 * 0.7071067811865476f));
            h[t][1] = 0.5f * g01 * (1.f + erff(g01 * 0.7071067811865476f));
            h[t][2] = 0.5f * g10 * (1.f + erff(g10 * 0.7071067811865476f));
            h[t][3] = 0.5f * g11 * (1.f + erff(g11 * 0.7071067811865476f));
        }

        // ---- GEMM2: m = g @ W2 (C-layout -> A-frags via quad shuffles) ----
        float m[8][4];
#pragma unroll
        for (int t = 0; t < 8; t++)
            m[t][0] = m[t][1] = m[t][2] = m[t][3] = 0.f;

        const int srcA = (lane & ~3) | (q >> 1);
        const int srcB = srcA + 2;
#pragma unroll
        for (int s = 0; s < 8; s++) {
            float t00 = __shfl_sync(FULL, h[s][0], srcA);
            float t01 = __shfl_sync(FULL, h[s][1], srcA);
            float t10 = __shfl_sync(FULL, h[s][2], srcA);
            float t11 = __shfl_sync(FULL, h[s][3], srcA);
            float u00 = __shfl_sync(FULL, h[s][0], srcB);
            float u01 = __shfl_sync(FULL, h[s][1], srcB);
            float u10 = __shfl_sync(FULL, h[s][2], srcB);
            float u11 = __shfl_sync(FULL, h[s][3], srcB);
            unsigned a0 = f2tf32((q & 1) ? t01 : t00);
            unsigned a1 = f2tf32((q & 1) ? t11 : t10);
            unsigned a2 = f2tf32((q & 1) ? u01 : u00);
            unsigned a3 = f2tf32((q & 1) ? u11 : u10);
#pragma unroll
            for (int t = 0; t < 8; t++) {
                uint2 b = sW2p[(s * 8 + t) * 32 + lane];
                mma_tf32(m[t], a0, a1, a2, a3, b.x, b.y);
            }
        }

        // ---- v4 scatter-add: pair channels across quad-neighbor lanes ----
#pragma unroll
        for (int t = 0; t < 8; t++) {
            int c = 8 * t + 2 * q;
            float p0 = m[t][0] + sb2[c], p1 = m[t][1] + sb2[c + 1];
            float e0 = __shfl_xor_sync(FULL, p0, 1);
            float e1 = __shfl_xor_sync(FULL, p1, 1);
            float q2 = m[t][2] + sb2[c], q3 = m[t][3] + sb2[c + 1];
            float e2 = __shfl_xor_sync(FULL, q2, 1);
            float e3 = __shfl_xor_sync(FULL, q3, 1);
            if ((q & 1) == 0) {
                if (v0) {
                    float* dst = out + (size_t)j0 * CH + 8 * t + 2 * q;
                    asm volatile("red.global.add.v4.f32 [%0], {%1,%2,%3,%4};"
                                 :: "l"(dst), "f"(p0), "f"(p1), "f"(e0), "f"(e1)
                                 : "memory");
                }
            } else {
                if (v1) {
                    float* dst = out + (size_t)j1 * CH + 8 * t + 2 * (q - 1);
                    asm volatile("red.global.add.v4.f32 [%0], {%1,%2,%3,%4};"
                                 :: "l"(dst), "f"(e2), "f"(e3), "f"(q2), "f"(q3)
                                 : "memory");
                }
            }
        }
    }
}

// ---------------------------------------------------------------------------
extern "C" void kernel_launch(void* const* d_in, const int* in_sizes, int n_in,
                              void* d_out, int out_size) {
    const float* x     = (const float*)d_in[0];
    const void*  ei    = d_in[1];
    const float* ea    = (const float*)d_in[2];
    const float* W1    = (const float*)d_in[3];
    const float* b1    = (const float*)d_in[4];
    const float* gamma = (const float*)d_in[5];
    const float* beta  = (const float*)d_in[6];
    const float* W2    = (const float*)d_in[7];
    const float* b2    = (const float*)d_in[8];
    float* out = (float*)d_out;

    int n_nodes = in_sizes[0] / CH;
    int n_edges = in_sizes[2] / 32;

    detect_kernel<<<1, 1>>>((const unsigned*)ei);

    int n4 = out_size / 4;
    zero_kernel<<<(n4 + 255) / 256, 256>>>((float4*)out, n4);

    int n_node_tiles = (n_nodes + 15) / 16;
    node_precompute<<<(n_node_tiles + 7) / 8, 256>>>(x, W1, n_nodes);

    edge_kernel<<<NBLK, 256>>>(ei, ea, W1, b1, gamma, beta, W2, b2, out, n_edges);
}